// round 16
// baseline (speedup 1.0000x reference)
#include <cuda_runtime.h>
#include <cuda_fp16.h>
#include <math.h>
#include <stdint.h>

#define N_NODES 20000
#define NPAD    20096            // 157 * 128
#define N_EDGES 320000
#define HDIM    256
#define S_STEPS 4

typedef __half h16;

// ---------------- device-global scratch (module-load allocated) -------------
__device__ h16   g_Y  [NPAD * 512];      // [hn | agg] fp16
__device__ h16   g_ABf[NPAD * 512];      // [A | B] per node (fp16)
__device__ h16   g_Cf [(size_t)N_EDGES * 256];  // ea@W1c + b1, dst-sorted order
__device__ h16   g_Pf [NPAD * 256];      // segsum(silu(hidden)) fp16 (pad rows 0)
__device__ float g_G  [NPAD * 256];      // P @ eW2
__device__ h16   g_T  [NPAD * 512];      // silu(y@nW1+nb1) fp16
__device__ h16   g_eas[(size_t)N_EDGES * 64];   // edge_attr fp16 (dst-sorted)
// transposed fp16 weights, per step ([N,K] row-major)
__device__ h16   g_W1 [4 * 512 * 256];
__device__ h16   g_Wc [4 * 256 * 64];
__device__ h16   g_W2 [4 * 256 * 256];
__device__ h16   g_N1 [4 * 512 * 512];
__device__ h16   g_N2 [4 * 256 * 512];
__device__ float g_deg [N_NODES];
__device__ int   g_degi[N_NODES];
__device__ int   g_cnt [N_NODES];
__device__ int   g_start[N_NODES + 1];
__device__ int   g_src [N_EDGES];
__device__ int   g_dst [N_EDGES];
__device__ int   g_srcs[N_EDGES];        // src in dst-sorted order
__device__ int   g_pos [N_EDGES];        // e -> sorted position
__device__ int   g_bsum[81];
__device__ int   g_boff[81];
__device__ int   g_is64;

__device__ __forceinline__ float silu_f(float v) {
    return __fdividef(v, 1.0f + __expf(-v));
}

__device__ __forceinline__ uint32_t smem_u32(const void* p) {
    uint32_t a;
    asm("{ .reg .u64 t; cvta.to.shared.u64 t, %1; cvt.u32.u64 %0, t; }"
        : "=r"(a) : "l"(p));
    return a;
}

// ====================== small elementwise kernels ============================
__global__ void zero_detect(const long long* __restrict__ p) {
    int i = blockIdx.x * blockDim.x + threadIdx.x;
    if (i < N_NODES) { g_degi[i] = 0; g_cnt[i] = 0; }
    if (blockIdx.x == 0) {
        __shared__ int bad;
        if (threadIdx.x == 0) bad = 0;
        __syncthreads();
        if (threadIdx.x < 64) {
            long long v = p[threadIdx.x];
            if (v < 0 || v >= N_NODES) bad = 1;
        }
        __syncthreads();
        if (threadIdx.x == 0) g_is64 = bad ? 0 : 1;
    }
}

__global__ void convert_idx_kernel(const void* __restrict__ ei) {
    int e = blockIdx.x * blockDim.x + threadIdx.x;
    if (e >= N_EDGES) return;
    int s, d;
    if (g_is64) {
        const long long* p = (const long long*)ei;
        s = (int)p[e]; d = (int)p[N_EDGES + e];
    } else {
        const int* p = (const int*)ei;
        s = p[e]; d = p[N_EDGES + e];
    }
    g_src[e] = s; g_dst[e] = d;
    atomicAdd(&g_degi[d], 1);
}

// hierarchical scan: 80 chunks of 250 nodes
#define SCB 80
#define SCCH 250
// A: per-chunk sums
__global__ void scanA() {
    const int b = blockIdx.x, t = threadIdx.x;
    const int i = b * SCCH + t;
    int v = (t < SCCH && i < N_NODES) ? g_degi[i] : 0;
    // block reduce (256 threads)
    __shared__ int sm[256];
    sm[t] = v;
    __syncthreads();
    #pragma unroll
    for (int off = 128; off; off >>= 1) {
        if (t < off) sm[t] += sm[t + off];
        __syncthreads();
    }
    if (t == 0) g_bsum[b] = sm[0];
}
// B: exclusive scan of 80 partials (1 block, 128 threads)
__global__ void scanB() {
    const int t = threadIdx.x;
    __shared__ int sm[128];
    int v = (t < SCB) ? g_bsum[t] : 0;
    sm[t] = v;
    __syncthreads();
    for (int off = 1; off < 128; off <<= 1) {
        int u = (t >= off) ? sm[t - off] : 0;
        __syncthreads();
        sm[t] += u;
        __syncthreads();
    }
    if (t < SCB) g_boff[t] = sm[t] - v;
    if (t == SCB - 1) g_start[N_NODES] = sm[t];
}
// C: per-chunk local exclusive scan + chunk offset; emits g_start, g_deg
__global__ void scanC() {
    const int b = blockIdx.x, t = threadIdx.x;
    const int i = b * SCCH + t;
    int v = (t < SCCH && i < N_NODES) ? g_degi[i] : 0;
    __shared__ int sm[256];
    sm[t] = v;
    __syncthreads();
    for (int off = 1; off < 256; off <<= 1) {
        int u = (t >= off) ? sm[t - off] : 0;
        __syncthreads();
        sm[t] += u;
        __syncthreads();
    }
    if (t < SCCH && i < N_NODES) {
        g_start[i] = g_boff[b] + sm[t] - v;   // exclusive
        g_deg[i] = (float)v;
    }
}

__global__ void perm_kernel() {
    int e = blockIdx.x * blockDim.x + threadIdx.x;
    if (e >= N_EDGES) return;
    int d = g_dst[e];
    int pos = g_start[d] + atomicAdd(&g_cnt[d], 1);
    g_pos[e] = pos;
    g_srcs[pos] = g_src[e];
}

// convert fp32 edge_attr -> fp16 directly into dst-sorted order
__global__ void cvt_sorted_kernel(const float* __restrict__ ea) {
    long idx = (long)blockIdx.x * blockDim.x + threadIdx.x;   // E * 8
    int e = (int)(idx >> 3), q = (int)idx & 7;
    if (e >= N_EDGES) return;
    const float4 f0 = *(const float4*)&ea[(long)e * 64 + q * 8];
    const float4 f1 = *(const float4*)&ea[(long)e * 64 + q * 8 + 4];
    uint4 out;
    out.x = ((uint32_t)__half_as_ushort(__float2half(f0.y)) << 16) |
            __half_as_ushort(__float2half(f0.x));
    out.y = ((uint32_t)__half_as_ushort(__float2half(f0.w)) << 16) |
            __half_as_ushort(__float2half(f0.z));
    out.z = ((uint32_t)__half_as_ushort(__float2half(f1.y)) << 16) |
            __half_as_ushort(__float2half(f1.x));
    out.w = ((uint32_t)__half_as_ushort(__float2half(f1.w)) << 16) |
            __half_as_ushort(__float2half(f1.z));
    ((uint4*)g_eas)[(long)g_pos[e] * 8 + q] = out;
}

// one launch transposes+converts ALL per-step weights (fp16).
__global__ void tsplit_all(const float* __restrict__ eW1,
                           const float* __restrict__ eW2,
                           const float* __restrict__ nW1,
                           const float* __restrict__ nW2) {
    const int z = blockIdx.z;
    const int step = z / 6, mat = z % 6;
    const float* W; int K, N; h16 *oh;
    switch (mat) {
    case 0: W = eW1 + (long)step * 576 * 256;             K = 256; N = 256;
            oh = g_W1 + (long)step * 512 * 256;            break;
    case 1: W = eW1 + (long)step * 576 * 256 + 256 * 256; K = 256; N = 256;
            oh = g_W1 + (long)step * 512 * 256 + 256*256;  break;
    case 2: W = eW1 + (long)step * 576 * 256 + 512 * 256; K = 64;  N = 256;
            oh = g_Wc + (long)step * 256 * 64;             break;
    case 3: W = eW2 + (long)step * 256 * 256;             K = 256; N = 256;
            oh = g_W2 + (long)step * 256 * 256;            break;
    case 4: W = nW1 + (long)step * 512 * 512;             K = 512; N = 512;
            oh = g_N1 + (long)step * 512 * 512;            break;
    default:W = nW2 + (long)step * 512 * 256;             K = 512; N = 256;
            oh = g_N2 + (long)step * 256 * 512;            break;
    }
    const int k0 = blockIdx.y * 32, n0 = blockIdx.x * 32;
    if (k0 >= K || n0 >= N) return;
    __shared__ float tile[32][33];
    const int tx = threadIdx.x, ty = threadIdx.y;   // 32 x 8
    #pragma unroll
    for (int i = 0; i < 32; i += 8) {
        int k = k0 + ty + i, n = n0 + tx;
        tile[ty + i][tx] = (k < K && n < N) ? W[(long)k * N + n] : 0.0f;
    }
    __syncthreads();
    #pragma unroll
    for (int i = 0; i < 32; i += 8) {
        int n = n0 + ty + i, k = k0 + tx;
        if (n < N && k < K)
            oh[(long)n * K + k] = __float2half(tile[tx][ty + i]);
    }
}

// ---------------- layer norm -> fp16 output ----------------------------------
__global__ void ln_kernel(const float* __restrict__ x, long ldx,
                          const float* __restrict__ gamma,
                          const float* __restrict__ beta,
                          const float* __restrict__ preBias,
                          const float* __restrict__ deg,
                          h16* __restrict__ out, long ldo, int colOff) {
    int n = blockIdx.x, t = threadIdx.x;
    float v = x[(long)n * ldx + t];
    if (deg) v = v / fmaxf(deg[n], 1.0f) + preBias[t];
    float s = v, s2 = v * v;
    #pragma unroll
    for (int o = 16; o; o >>= 1) {
        s  += __shfl_xor_sync(0xFFFFFFFFu, s,  o);
        s2 += __shfl_xor_sync(0xFFFFFFFFu, s2, o);
    }
    __shared__ float as[8], as2[8];
    int w = t >> 5, l = t & 31;
    if (l == 0) { as[w] = s; as2[w] = s2; }
    __syncthreads();
    float S = 0.f, S2 = 0.f;
    #pragma unroll
    for (int i = 0; i < 8; i++) { S += as[i]; S2 += as2[i]; }
    float mean = S * (1.0f / 256.0f);
    float var  = S2 * (1.0f / 256.0f) - mean * mean;
    float rstd = rsqrtf(var + 1e-5f);
    float r = (v - mean) * rstd * gamma[t] + beta[t];
    out[(long)n * ldo + colOff + t] = __float2half(r);
}

// ====================== shared MMA macros ====================================
#define LDSM4(R, ADDR) \
    asm volatile("ldmatrix.sync.aligned.m8n8.x4.shared.b16 {%0,%1,%2,%3}, [%4];" \
                 : "=r"((R)[0]), "=r"((R)[1]), "=r"((R)[2]), "=r"((R)[3]) : "r"(ADDR))

#define MMA16816(C, A, B0, B1) \
    asm volatile("mma.sync.aligned.m16n8k16.row.col.f32.f16.f16.f32 " \
                 "{%0,%1,%2,%3}, {%4,%5,%6,%7}, {%8,%9}, {%0,%1,%2,%3};" \
                 : "+f"((C)[0]), "+f"((C)[1]), "+f"((C)[2]), "+f"((C)[3]) \
                 : "r"((A)[0]), "r"((A)[1]), "r"((A)[2]), "r"((A)[3]), \
                   "r"(B0), "r"(B1))

#define CP16(DST, SRC) \
    asm volatile("cp.async.cg.shared.global [%0], [%1], 16;" :: "r"(DST), "l"(SRC))

// ============== HMMA fp16 GEMM: Out = op(A@W^T + bias) =======================
// BM=128, BN=128, BK=64, 256 threads (8 warps = 2Mx4N, warp tile 64x32).
// 2-stage cp.async double buffer.  K % 64 == 0.  2 CTAs/SM (72KB smem).
#define PITCH 144
#define S_A  0
#define S_B  18432
#define STAGE 36864
#define GEMM_SMEM (2 * STAGE)

__global__ void __launch_bounds__(256, 2)
mma_gemm(const h16* __restrict__ A, long lda,
         const h16* __restrict__ B, long ldb,
         const float* __restrict__ bias,
         float* __restrict__ Out, h16* __restrict__ OutF,
         const float* __restrict__ AccIn,
         long ldo, int M, int K, int act, int accum) {
    extern __shared__ char smem[];
    const uint32_t sb = smem_u32(smem);
    const int tid  = threadIdx.x;
    const int lane = tid & 31;
    const int wid  = tid >> 5;
    const long bm = (long)blockIdx.y * 128;
    const long bn = (long)blockIdx.x * 128;
    const int wm = (wid & 1) * 64;
    const int wn = (wid >> 1) * 32;

    float acc[4][4][4];
    #pragma unroll
    for (int i = 0; i < 4; i++)
        #pragma unroll
        for (int j = 0; j < 4; j++)
            #pragma unroll
            for (int q = 0; q < 4; q++) acc[i][j][q] = 0.0f;

    const int nk = K >> 6;
    const int lrow = tid >> 1;            // 0..127
    const int lcb  = (tid & 1) * 64;      // byte offset 0/64 within 128B row

    #define ISSUE(kt) do {                                                     \
        const uint32_t st = sb + ((kt) & 1) * STAGE;                           \
        const long k0 = (long)(kt) << 6;                                       \
        _Pragma("unroll")                                                      \
        for (int i = 0; i < 4; i++) {                                          \
            CP16(st + S_A + lrow * PITCH + lcb + i * 16,                       \
                 A + (bm + lrow) * lda + k0 + lcb / 2 + i * 8);                \
            CP16(st + S_B + lrow * PITCH + lcb + i * 16,                       \
                 B + (bn + lrow) * ldb + k0 + lcb / 2 + i * 8);                \
        }                                                                      \
        asm volatile("cp.async.commit_group;");                                \
    } while (0)

    ISSUE(0);

    const uint32_t a_off = (uint32_t)((wm + (lane & 15)) * PITCH + (lane >> 4) * 16);
    const uint32_t b_off = (uint32_t)((wn + (lane & 15)) * PITCH + (lane >> 4) * 16);

    for (int kt = 0; kt < nk; kt++) {
        if (kt + 1 < nk) {
            ISSUE(kt + 1);
            asm volatile("cp.async.wait_group 1;");
        } else {
            asm volatile("cp.async.wait_group 0;");
        }
        __syncthreads();
        const uint32_t st = sb + (kt & 1) * STAGE;
        #pragma unroll
        for (int h = 0; h < 4; h++) {
            uint32_t a[4][4];
            #pragma unroll
            for (int mi = 0; mi < 4; mi++)
                LDSM4(a[mi], st + S_A + a_off + mi * (16 * PITCH) + h * 32);
            uint32_t bq[2][4];
            #pragma unroll
            for (int jj = 0; jj < 2; jj++)
                LDSM4(bq[jj], st + S_B + b_off + jj * (16 * PITCH) + h * 32);
            #pragma unroll
            for (int mi = 0; mi < 4; mi++)
                #pragma unroll
                for (int j = 0; j < 4; j++) {
                    const int jj = j >> 1, jo = j & 1;
                    MMA16816(acc[mi][j], a[mi], bq[jj][jo], bq[jj][2 + jo]);
                }
        }
        __syncthreads();
    }

    const int r0 = lane >> 2;
    const int c0 = (lane & 3) * 2;
    float2 bv[4];
    if (bias) {
        #pragma unroll
        for (int j = 0; j < 4; j++)
            bv[j] = *(const float2*)&bias[bn + wn + j * 8 + c0];
    } else {
        #pragma unroll
        for (int j = 0; j < 4; j++) bv[j] = make_float2(0.f, 0.f);
    }
    #pragma unroll
    for (int mi = 0; mi < 4; mi++) {
        #pragma unroll
        for (int half = 0; half < 2; half++) {
            const long m = bm + wm + mi * 16 + r0 + half * 8;
            if (m >= M) continue;
            #pragma unroll
            for (int j = 0; j < 4; j++) {
                float x = acc[mi][j][half * 2 + 0] + bv[j].x;
                float y = acc[mi][j][half * 2 + 1] + bv[j].y;
                if (act) { x = silu_f(x); y = silu_f(y); }
                const long col = bn + wn + j * 8 + c0;
                if (OutF) {
                    uint32_t hw = ((uint32_t)__half_as_ushort(__float2half(y)) << 16) |
                                  __half_as_ushort(__float2half(x));
                    *(uint32_t*)(OutF + m * ldo + col) = hw;
                } else {
                    if (accum) {
                        float2 old = *(const float2*)(AccIn + m * ldo + col);
                        x += old.x; y += old.y;
                    }
                    *(float2*)(Out + m * ldo + col) = make_float2(x, y);
                }
            }
        }
    }
    #undef ISSUE
}

// ============ weights-stationary K=64 edge GEMM: Cf = ea@Wc^T + eb1 ==========
#define EP 144
#define EB_OFF 0
#define EA_OFF 18432
#define EA_BYTES 18432
#define EDGE_SMEM (18432 * 3)
#define EMT 8

__global__ void __launch_bounds__(256, 2)
edge_gemm_k64(const h16* __restrict__ A,   // [E, 64] dst-sorted ea
              const h16* __restrict__ B,   // [256, 64] Wc
              const float* __restrict__ bias,
              h16* __restrict__ OutF,      // [E, 256]
              int total_mt) {
    extern __shared__ char smem[];
    const uint32_t sb = smem_u32(smem);
    const int tid = threadIdx.x, lane = tid & 31, wid = tid >> 5;
    const int bn = blockIdx.x * 128;
    const int mt0 = blockIdx.y * EMT;
    const int nt = (total_mt - mt0 < EMT) ? (total_mt - mt0) : EMT;
    const int wm = (wid & 1) * 64;
    const int wn = (wid >> 1) * 32;

    const int lrow = tid >> 1;
    const int lcb  = (tid & 1) * 64;

    #pragma unroll
    for (int i = 0; i < 4; i++) {
        CP16(sb + EB_OFF + lrow * EP + lcb + i * 16,
             B + (bn + lrow) * 64 + lcb / 2 + i * 8);
    }
    #pragma unroll
    for (int i = 0; i < 4; i++) {
        CP16(sb + EA_OFF + lrow * EP + lcb + i * 16,
             A + ((long)mt0 * 128 + lrow) * 64 + lcb / 2 + i * 8);
    }
    asm volatile("cp.async.commit_group;");

    const uint32_t a_off = (uint32_t)((wm + (lane & 15)) * EP + (lane >> 4) * 16);
    const uint32_t b_off = (uint32_t)((lane & 15) * EP + (lane >> 4) * 16);

    const int r0 = lane >> 2;
    const int c0 = (lane & 3) * 2;
    float2 bv[4];
    #pragma unroll
    for (int j = 0; j < 4; j++)
        bv[j] = *(const float2*)&bias[bn + wn + j * 8 + c0];

    for (int t = 0; t < nt; t++) {
        if (t + 1 < nt) {
            const uint32_t ad = sb + EA_OFF + ((t + 1) & 1) * EA_BYTES;
            #pragma unroll
            for (int i = 0; i < 4; i++) {
                CP16(ad + lrow * EP + lcb + i * 16,
                     A + ((long)(mt0 + t + 1) * 128 + lrow) * 64 + lcb / 2 + i * 8);
            }
            asm volatile("cp.async.commit_group;");
            asm volatile("cp.async.wait_group 1;");
        } else {
            asm volatile("cp.async.wait_group 0;");
        }
        __syncthreads();

        float acc[4][4][4];
        #pragma unroll
        for (int i = 0; i < 4; i++)
            #pragma unroll
            for (int j = 0; j < 4; j++)
                #pragma unroll
                for (int q = 0; q < 4; q++) acc[i][j][q] = 0.0f;

        const uint32_t ab = sb + EA_OFF + (t & 1) * EA_BYTES;
        #pragma unroll
        for (int h = 0; h < 4; h++) {
            uint32_t a[4][4];
            #pragma unroll
            for (int mi = 0; mi < 4; mi++)
                LDSM4(a[mi], ab + a_off + mi * (16 * EP) + h * 32);
            uint32_t bq[2][4];
            #pragma unroll
            for (int jj = 0; jj < 2; jj++)
                LDSM4(bq[jj], sb + EB_OFF + b_off + (wn + jj * 16) * EP + h * 32);
            #pragma unroll
            for (int mi = 0; mi < 4; mi++)
                #pragma unroll
                for (int j = 0; j < 4; j++) {
                    const int jj = j >> 1, jo = j & 1;
                    MMA16816(acc[mi][j], a[mi], bq[jj][jo], bq[jj][2 + jo]);
                }
        }

        const long ebase = (long)(mt0 + t) * 128;
        #pragma unroll
        for (int mi = 0; mi < 4; mi++) {
            #pragma unroll
            for (int half = 0; half < 2; half++) {
                const long m = ebase + wm + mi * 16 + r0 + half * 8;
                #pragma unroll
                for (int j = 0; j < 4; j++) {
                    float x = acc[mi][j][half * 2 + 0] + bv[j].x;
                    float y = acc[mi][j][half * 2 + 1] + bv[j].y;
                    const long col = bn + wn + j * 8 + c0;
                    uint32_t hw = ((uint32_t)__half_as_ushort(__float2half(y)) << 16) |
                                  __half_as_ushort(__float2half(x));
                    *(uint32_t*)(OutF + m * 256 + col) = hw;
                }
            }
        }
        __syncthreads();
    }
}

// ====== combine (dst-sorted segmented reduction, no atomics) =================
__global__ void combine_sorted() {
    const int d = blockIdx.x;
    const int col = threadIdx.x;
    const float b = __half2float(g_ABf[(long)d * 512 + 256 + col]);
    const int k0 = g_start[d];
    const int k1 = g_start[d + 1];
    float acc = 0.0f;
    int k = k0;
    for (; k + 2 <= k1; k += 2) {
        const int s0 = g_srcs[k];
        const int s1 = g_srcs[k + 1];
        const float a0 = __half2float(g_ABf[(long)s0 * 512 + col]);
        const float c0 = __half2float(g_Cf[(long)k * 256 + col]);
        const float a1 = __half2float(g_ABf[(long)s1 * 512 + col]);
        const float c1 = __half2float(g_Cf[(long)(k + 1) * 256 + col]);
        acc += silu_f(a0 + b + c0);
        acc += silu_f(a1 + b + c1);
    }
    if (k < k1) {
        const int s0 = g_srcs[k];
        const float a0 = __half2float(g_ABf[(long)s0 * 512 + col]);
        const float c0 = __half2float(g_Cf[(long)k * 256 + col]);
        acc += silu_f(a0 + b + c0);
    }
    g_Pf[(long)d * 256 + col] = __float2half(acc);
}

// ============================ launch =========================================
extern "C" void kernel_launch(void* const* d_in, const int* in_sizes, int n_in,
                              void* d_out, int out_size) {
    const float* node_state = (const float*)d_in[0];
    const float* edge_attr  = (const float*)d_in[1];
    const float* nn_g = (const float*)d_in[2];
    const float* nn_b = (const float*)d_in[3];
    const float* mn_g = (const float*)d_in[4];
    const float* mn_b = (const float*)d_in[5];
    const float* eW1  = (const float*)d_in[6];
    const float* eb1  = (const float*)d_in[7];
    const float* eW2  = (const float*)d_in[8];
    const float* eb2  = (const float*)d_in[9];
    const float* nW1  = (const float*)d_in[10];
    const float* nb1  = (const float*)d_in[11];
    const float* nW2  = (const float*)d_in[12];
    const float* nb2  = (const float*)d_in[13];
    const void*  eidx = d_in[14];
    float* h = (float*)d_out;

    static bool inited = false;
    static cudaStream_t s1;
    static cudaEvent_t evPrep, evG3, evCfree;
    if (!inited) {
        cudaStreamCreateWithFlags(&s1, cudaStreamNonBlocking);
        cudaEventCreateWithFlags(&evPrep,  cudaEventDisableTiming);
        cudaEventCreateWithFlags(&evG3,    cudaEventDisableTiming);
        cudaEventCreateWithFlags(&evCfree, cudaEventDisableTiming);
        cudaFuncSetAttribute(mma_gemm, cudaFuncAttributeMaxDynamicSharedMemorySize,
                             GEMM_SMEM);
        cudaFuncSetAttribute(edge_gemm_k64,
                             cudaFuncAttributeMaxDynamicSharedMemorySize, EDGE_SMEM);
        inited = true;
    }

    void *pY, *pABf, *pCf, *pPf, *pG, *pT, *pEas,
         *pW1, *pWc, *pW2, *pN1, *pN2, *pdeg;
    cudaGetSymbolAddress(&pY, g_Y);     cudaGetSymbolAddress(&pABf, g_ABf);
    cudaGetSymbolAddress(&pCf, g_Cf);   cudaGetSymbolAddress(&pPf, g_Pf);
    cudaGetSymbolAddress(&pG, g_G);     cudaGetSymbolAddress(&pT, g_T);
    cudaGetSymbolAddress(&pEas, g_eas);
    cudaGetSymbolAddress(&pW1, g_W1);   cudaGetSymbolAddress(&pWc, g_Wc);
    cudaGetSymbolAddress(&pW2, g_W2);   cudaGetSymbolAddress(&pN1, g_N1);
    cudaGetSymbolAddress(&pN2, g_N2);   cudaGetSymbolAddress(&pdeg, g_deg);

    h16 *Y=(h16*)pY, *ABf=(h16*)pABf, *Cf=(h16*)pCf, *Pf=(h16*)pPf,
        *T=(h16*)pT, *Eas=(h16*)pEas,
        *W1=(h16*)pW1, *Wc=(h16*)pWc, *W2=(h16*)pW2, *N1=(h16*)pN1,
        *N2=(h16*)pN2;
    float *G=(float*)pG, *deg=(float*)pdeg;

    const int MT = NPAD / 128;                 // 157 node M-tiles
    const int ETOT = N_EDGES / 128;            // 2500 edge M-tiles
    const int EGY = (ETOT + EMT - 1) / EMT;    // 313

    // ---- prep: idx chain on stream 0, weight transpose on s1 (independent) --
    tsplit_all<<<dim3(16, 16, 24), dim3(32, 8), 0, s1>>>(eW1, eW2, nW1, nW2);
    zero_detect<<<(N_NODES + 255) / 256, 256>>>((const long long*)eidx);
    convert_idx_kernel<<<(N_EDGES + 255) / 256, 256>>>(eidx);
    scanA<<<SCB, 256>>>();
    scanB<<<1, 128>>>();
    scanC<<<SCB, 256>>>();
    perm_kernel<<<(N_EDGES + 255) / 256, 256>>>();
    cvt_sorted_kernel<<<((long)N_EDGES * 8 + 255) / 256, 256>>>(edge_attr);
    cudaEventRecord(evPrep, 0);

    // G3(step 0) on s1 (after its own tsplit and main-stream prep)
    cudaStreamWaitEvent(s1, evPrep, 0);
    edge_gemm_k64<<<dim3(2, EGY), 256, EDGE_SMEM, s1>>>(
        Eas, Wc, eb1, Cf, ETOT);
    cudaEventRecord(evG3, s1);

    for (int i = 0; i < S_STEPS; i++) {
        const float* hin = (i == 0) ? node_state : h;

        // main stream: ln -> GEMM-2 (fp16 AB out)
        ln_kernel<<<N_NODES, 256>>>(hin, 256, nn_g + i * HDIM, nn_b + i * HDIM,
                                    nullptr, nullptr, Y, 512, 0);
        mma_gemm<<<dim3(4, MT), 256, GEMM_SMEM>>>(
            Y, 512, W1 + (long)i * 512 * 256, 256,
            nullptr, nullptr, ABf, nullptr, 512, N_NODES, 256, 0, 0);

        // combine (needs this step's Cf)
        cudaStreamWaitEvent(0, evG3, 0);
        combine_sorted<<<N_NODES, 256>>>();
        cudaEventRecord(evCfree, 0);

        // issue NEXT step's edge GEMM on s1 — hides under G5..G8
        if (i + 1 < S_STEPS) {
            cudaStreamWaitEvent(s1, evCfree, 0);
            edge_gemm_k64<<<dim3(2, EGY), 256, EDGE_SMEM, s1>>>(
                Eas, Wc + (long)(i + 1) * 256 * 64, eb1 + (i + 1) * HDIM,
                Cf, ETOT);
            cudaEventRecord(evG3, s1);
        }

        // G5 -> ln -> G7 -> G8
        mma_gemm<<<dim3(2, MT), 256, GEMM_SMEM>>>(
            Pf, 256, W2 + (long)i * 256 * 256, 256,
            nullptr, G, nullptr, nullptr, 256, N_NODES, 256, 0, 0);
        ln_kernel<<<N_NODES, 256>>>(G, 256, mn_g + i * HDIM, mn_b + i * HDIM,
                                    eb2 + i * HDIM, deg, Y, 512, 256);
        mma_gemm<<<dim3(4, MT), 256, GEMM_SMEM>>>(
            Y, 512, N1 + (long)i * 512 * 512, 512,
            nb1 + i * 512, nullptr, T, nullptr, 512, N_NODES, 512, 1, 0);
        mma_gemm<<<dim3(2, MT), 256, GEMM_SMEM>>>(
            T, 512, N2 + (long)i * 256 * 512, 512,
            nb2 + i * HDIM, h, nullptr, hin, 256, N_NODES, 512, 0, 1);
    }
}

// round 17
// speedup vs baseline: 1.0592x; 1.0592x over previous
#include <cuda_runtime.h>
#include <cuda_fp16.h>
#include <math.h>
#include <stdint.h>

#define N_NODES 20000
#define NPAD    20096            // 157 * 128
#define N_EDGES 320000
#define HDIM    256
#define S_STEPS 4

typedef __half h16;

// ---------------- device-global scratch (module-load allocated) -------------
__device__ h16   g_Y  [NPAD * 512];      // [hn | agg] fp16
__device__ h16   g_ABf[NPAD * 512];      // [A | B] per node (fp16)
__device__ h16   g_Cf [(size_t)N_EDGES * 256];  // ea@W1c + b1, dst-sorted order
__device__ h16   g_Pf [NPAD * 256];      // segsum(silu(hidden)) fp16 (pad rows 0)
__device__ float g_G  [NPAD * 256];      // P @ eW2
__device__ h16   g_T  [NPAD * 512];      // silu(y@nW1+nb1) fp16
__device__ h16   g_eas[(size_t)N_EDGES * 64];   // edge_attr fp16 (dst-sorted)
// transposed fp16 weights, per step ([N,K] row-major)
__device__ h16   g_W1 [4 * 512 * 256];
__device__ h16   g_Wc [4 * 256 * 64];
__device__ h16   g_W2 [4 * 256 * 256];
__device__ h16   g_N1 [4 * 512 * 512];
__device__ h16   g_N2 [4 * 256 * 512];
__device__ float g_deg [N_NODES];
__device__ int   g_degi[N_NODES];
__device__ int   g_cnt [N_NODES];
__device__ int   g_start[N_NODES + 1];
__device__ int   g_src [N_EDGES];
__device__ int   g_dst [N_EDGES];
__device__ int   g_srcs[N_EDGES];        // src in dst-sorted order
__device__ int   g_pos [N_EDGES];        // e -> sorted position
__device__ int   g_bsum[81];
__device__ int   g_boff[81];
__device__ int   g_is64;

__device__ __forceinline__ float silu_f(float v) {
    return __fdividef(v, 1.0f + __expf(-v));
}

__device__ __forceinline__ uint32_t smem_u32(const void* p) {
    uint32_t a;
    asm("{ .reg .u64 t; cvta.to.shared.u64 t, %1; cvt.u32.u64 %0, t; }"
        : "=r"(a) : "l"(p));
    return a;
}

// ====================== small elementwise kernels ============================
__global__ void zero_detect(const long long* __restrict__ p) {
    int i = blockIdx.x * blockDim.x + threadIdx.x;
    if (i < N_NODES) { g_degi[i] = 0; g_cnt[i] = 0; }
    if (blockIdx.x == 0) {
        __shared__ int bad;
        if (threadIdx.x == 0) bad = 0;
        __syncthreads();
        if (threadIdx.x < 64) {
            long long v = p[threadIdx.x];
            if (v < 0 || v >= N_NODES) bad = 1;
        }
        __syncthreads();
        if (threadIdx.x == 0) g_is64 = bad ? 0 : 1;
    }
}

__global__ void convert_idx_kernel(const void* __restrict__ ei) {
    int e = blockIdx.x * blockDim.x + threadIdx.x;
    if (e >= N_EDGES) return;
    int s, d;
    if (g_is64) {
        const long long* p = (const long long*)ei;
        s = (int)p[e]; d = (int)p[N_EDGES + e];
    } else {
        const int* p = (const int*)ei;
        s = p[e]; d = p[N_EDGES + e];
    }
    g_src[e] = s; g_dst[e] = d;
    atomicAdd(&g_degi[d], 1);
}

// hierarchical scan: 80 chunks of 250 nodes
#define SCB 80
#define SCCH 250
__global__ void scanA() {
    const int b = blockIdx.x, t = threadIdx.x;
    const int i = b * SCCH + t;
    int v = (t < SCCH && i < N_NODES) ? g_degi[i] : 0;
    __shared__ int sm[256];
    sm[t] = v;
    __syncthreads();
    #pragma unroll
    for (int off = 128; off; off >>= 1) {
        if (t < off) sm[t] += sm[t + off];
        __syncthreads();
    }
    if (t == 0) g_bsum[b] = sm[0];
}
__global__ void scanB() {
    const int t = threadIdx.x;
    __shared__ int sm[128];
    int v = (t < SCB) ? g_bsum[t] : 0;
    sm[t] = v;
    __syncthreads();
    for (int off = 1; off < 128; off <<= 1) {
        int u = (t >= off) ? sm[t - off] : 0;
        __syncthreads();
        sm[t] += u;
        __syncthreads();
    }
    if (t < SCB) g_boff[t] = sm[t] - v;
    if (t == SCB - 1) g_start[N_NODES] = sm[t];
}
__global__ void scanC() {
    const int b = blockIdx.x, t = threadIdx.x;
    const int i = b * SCCH + t;
    int v = (t < SCCH && i < N_NODES) ? g_degi[i] : 0;
    __shared__ int sm[256];
    sm[t] = v;
    __syncthreads();
    for (int off = 1; off < 256; off <<= 1) {
        int u = (t >= off) ? sm[t - off] : 0;
        __syncthreads();
        sm[t] += u;
        __syncthreads();
    }
    if (t < SCCH && i < N_NODES) {
        g_start[i] = g_boff[b] + sm[t] - v;   // exclusive
        g_deg[i] = (float)v;
    }
}

__global__ void perm_kernel() {
    int e = blockIdx.x * blockDim.x + threadIdx.x;
    if (e >= N_EDGES) return;
    int d = g_dst[e];
    int pos = g_start[d] + atomicAdd(&g_cnt[d], 1);
    g_pos[e] = pos;
    g_srcs[pos] = g_src[e];
}

// convert fp32 edge_attr -> fp16 directly into dst-sorted order
__global__ void cvt_sorted_kernel(const float* __restrict__ ea) {
    long idx = (long)blockIdx.x * blockDim.x + threadIdx.x;   // E * 8
    int e = (int)(idx >> 3), q = (int)idx & 7;
    if (e >= N_EDGES) return;
    const float4 f0 = *(const float4*)&ea[(long)e * 64 + q * 8];
    const float4 f1 = *(const float4*)&ea[(long)e * 64 + q * 8 + 4];
    uint4 out;
    out.x = ((uint32_t)__half_as_ushort(__float2half(f0.y)) << 16) |
            __half_as_ushort(__float2half(f0.x));
    out.y = ((uint32_t)__half_as_ushort(__float2half(f0.w)) << 16) |
            __half_as_ushort(__float2half(f0.z));
    out.z = ((uint32_t)__half_as_ushort(__float2half(f1.y)) << 16) |
            __half_as_ushort(__float2half(f1.x));
    out.w = ((uint32_t)__half_as_ushort(__float2half(f1.w)) << 16) |
            __half_as_ushort(__float2half(f1.z));
    ((uint4*)g_eas)[(long)g_pos[e] * 8 + q] = out;
}

// one launch transposes+converts ALL per-step weights (fp16).
__global__ void tsplit_all(const float* __restrict__ eW1,
                           const float* __restrict__ eW2,
                           const float* __restrict__ nW1,
                           const float* __restrict__ nW2) {
    const int z = blockIdx.z;
    const int step = z / 6, mat = z % 6;
    const float* W; int K, N; h16 *oh;
    switch (mat) {
    case 0: W = eW1 + (long)step * 576 * 256;             K = 256; N = 256;
            oh = g_W1 + (long)step * 512 * 256;            break;
    case 1: W = eW1 + (long)step * 576 * 256 + 256 * 256; K = 256; N = 256;
            oh = g_W1 + (long)step * 512 * 256 + 256*256;  break;
    case 2: W = eW1 + (long)step * 576 * 256 + 512 * 256; K = 64;  N = 256;
            oh = g_Wc + (long)step * 256 * 64;             break;
    case 3: W = eW2 + (long)step * 256 * 256;             K = 256; N = 256;
            oh = g_W2 + (long)step * 256 * 256;            break;
    case 4: W = nW1 + (long)step * 512 * 512;             K = 512; N = 512;
            oh = g_N1 + (long)step * 512 * 512;            break;
    default:W = nW2 + (long)step * 512 * 256;             K = 512; N = 256;
            oh = g_N2 + (long)step * 256 * 512;            break;
    }
    const int k0 = blockIdx.y * 32, n0 = blockIdx.x * 32;
    if (k0 >= K || n0 >= N) return;
    __shared__ float tile[32][33];
    const int tx = threadIdx.x, ty = threadIdx.y;   // 32 x 8
    #pragma unroll
    for (int i = 0; i < 32; i += 8) {
        int k = k0 + ty + i, n = n0 + tx;
        tile[ty + i][tx] = (k < K && n < N) ? W[(long)k * N + n] : 0.0f;
    }
    __syncthreads();
    #pragma unroll
    for (int i = 0; i < 32; i += 8) {
        int n = n0 + ty + i, k = k0 + tx;
        if (n < N && k < K)
            oh[(long)n * K + k] = __float2half(tile[tx][ty + i]);
    }
}

// ---------------- layer norm -> fp16 output ----------------------------------
__global__ void ln_kernel(const float* __restrict__ x, long ldx,
                          const float* __restrict__ gamma,
                          const float* __restrict__ beta,
                          const float* __restrict__ preBias,
                          const float* __restrict__ deg,
                          h16* __restrict__ out, long ldo, int colOff) {
    int n = blockIdx.x, t = threadIdx.x;
    float v = x[(long)n * ldx + t];
    if (deg) v = v / fmaxf(deg[n], 1.0f) + preBias[t];
    float s = v, s2 = v * v;
    #pragma unroll
    for (int o = 16; o; o >>= 1) {
        s  += __shfl_xor_sync(0xFFFFFFFFu, s,  o);
        s2 += __shfl_xor_sync(0xFFFFFFFFu, s2, o);
    }
    __shared__ float as[8], as2[8];
    int w = t >> 5, l = t & 31;
    if (l == 0) { as[w] = s; as2[w] = s2; }
    __syncthreads();
    float S = 0.f, S2 = 0.f;
    #pragma unroll
    for (int i = 0; i < 8; i++) { S += as[i]; S2 += as2[i]; }
    float mean = S * (1.0f / 256.0f);
    float var  = S2 * (1.0f / 256.0f) - mean * mean;
    float rstd = rsqrtf(var + 1e-5f);
    float r = (v - mean) * rstd * gamma[t] + beta[t];
    out[(long)n * ldo + colOff + t] = __float2half(r);
}

// ====================== shared MMA macros ====================================
#define LDSM4(R, ADDR) \
    asm volatile("ldmatrix.sync.aligned.m8n8.x4.shared.b16 {%0,%1,%2,%3}, [%4];" \
                 : "=r"((R)[0]), "=r"((R)[1]), "=r"((R)[2]), "=r"((R)[3]) : "r"(ADDR))

#define MMA16816(C, A, B0, B1) \
    asm volatile("mma.sync.aligned.m16n8k16.row.col.f32.f16.f16.f32 " \
                 "{%0,%1,%2,%3}, {%4,%5,%6,%7}, {%8,%9}, {%0,%1,%2,%3};" \
                 : "+f"((C)[0]), "+f"((C)[1]), "+f"((C)[2]), "+f"((C)[3]) \
                 : "r"((A)[0]), "r"((A)[1]), "r"((A)[2]), "r"((A)[3]), \
                   "r"(B0), "r"(B1))

#define CP16(DST, SRC) \
    asm volatile("cp.async.cg.shared.global [%0], [%1], 16;" :: "r"(DST), "l"(SRC))

// ============== HMMA fp16 GEMM: Out = op(A@W^T + bias) =======================
// BM=128, BN=128, BK=32, 256 threads (8 warps = 2Mx4N, warp tile 64x32).
// 3-stage cp.async pipeline (prefetch distance 2).  2 CTAs/SM.
#define PITCH 80
#define S_A  0
#define S_B  10240
#define STAGE 20480
#define GEMM_SMEM (3 * STAGE)

__global__ void __launch_bounds__(256, 2)
mma_gemm(const h16* __restrict__ A, long lda,
         const h16* __restrict__ B, long ldb,
         const float* __restrict__ bias,
         float* __restrict__ Out, h16* __restrict__ OutF,
         const float* __restrict__ AccIn,
         long ldo, int M, int K, int act, int accum) {
    extern __shared__ char smem[];
    const uint32_t sb = smem_u32(smem);
    const int tid  = threadIdx.x;
    const int lane = tid & 31;
    const int wid  = tid >> 5;
    const long bm = (long)blockIdx.y * 128;
    const long bn = (long)blockIdx.x * 128;
    const int wm = (wid & 1) * 64;
    const int wn = (wid >> 1) * 32;

    float acc[4][4][4];
    #pragma unroll
    for (int i = 0; i < 4; i++)
        #pragma unroll
        for (int j = 0; j < 4; j++)
            #pragma unroll
            for (int q = 0; q < 4; q++) acc[i][j][q] = 0.0f;

    const int nk = K >> 5;
    const int lrow0 = tid >> 2;
    const int lkc   = tid & 3;

    #define ISSUE(kt) do {                                                     \
        const uint32_t st = sb + ((kt) % 3) * STAGE;                           \
        const long k0 = (long)(kt) << 5;                                       \
        _Pragma("unroll")                                                      \
        for (int i = 0; i < 4; i++) {                                          \
            const int part = i >> 1;                                           \
            const int row = lrow0 + (i & 1) * 64;                              \
            const uint32_t d = st + part * 10240 + row * PITCH + lkc * 16;     \
            const h16* g = part == 0 ? A + (bm + row) * lda + k0 + lkc * 8     \
                                     : B + (bn + row) * ldb + k0 + lkc * 8;    \
            CP16(d, g);                                                        \
        }                                                                      \
        asm volatile("cp.async.commit_group;");                                \
    } while (0)

    ISSUE(0);
    ISSUE(1);

    const uint32_t a_off = (uint32_t)((wm + (lane & 15)) * PITCH + (lane >> 4) * 16);
    const uint32_t b_off = (uint32_t)((wn + (lane & 15)) * PITCH + (lane >> 4) * 16);

    for (int kt = 0; kt < nk; kt++) {
        if (kt + 1 < nk) {
            asm volatile("cp.async.wait_group 1;");
        } else {
            asm volatile("cp.async.wait_group 0;");
        }
        __syncthreads();
        if (kt + 2 < nk) ISSUE(kt + 2);
        const uint32_t st = sb + (kt % 3) * STAGE;
        #pragma unroll
        for (int h = 0; h < 2; h++) {
            uint32_t a[4][4];
            #pragma unroll
            for (int mi = 0; mi < 4; mi++)
                LDSM4(a[mi], st + S_A + a_off + mi * (16 * PITCH) + h * 32);
            uint32_t bq[2][4];
            #pragma unroll
            for (int jj = 0; jj < 2; jj++)
                LDSM4(bq[jj], st + S_B + b_off + jj * (16 * PITCH) + h * 32);
            #pragma unroll
            for (int mi = 0; mi < 4; mi++)
                #pragma unroll
                for (int j = 0; j < 4; j++) {
                    const int jj = j >> 1, jo = j & 1;
                    MMA16816(acc[mi][j], a[mi], bq[jj][jo], bq[jj][2 + jo]);
                }
        }
    }

    const int r0 = lane >> 2;
    const int c0 = (lane & 3) * 2;
    float2 bv[4];
    if (bias) {
        #pragma unroll
        for (int j = 0; j < 4; j++)
            bv[j] = *(const float2*)&bias[bn + wn + j * 8 + c0];
    } else {
        #pragma unroll
        for (int j = 0; j < 4; j++) bv[j] = make_float2(0.f, 0.f);
    }
    #pragma unroll
    for (int mi = 0; mi < 4; mi++) {
        #pragma unroll
        for (int half = 0; half < 2; half++) {
            const long m = bm + wm + mi * 16 + r0 + half * 8;
            if (m >= M) continue;
            #pragma unroll
            for (int j = 0; j < 4; j++) {
                float x = acc[mi][j][half * 2 + 0] + bv[j].x;
                float y = acc[mi][j][half * 2 + 1] + bv[j].y;
                if (act) { x = silu_f(x); y = silu_f(y); }
                const long col = bn + wn + j * 8 + c0;
                if (OutF) {
                    uint32_t hw = ((uint32_t)__half_as_ushort(__float2half(y)) << 16) |
                                  __half_as_ushort(__float2half(x));
                    *(uint32_t*)(OutF + m * ldo + col) = hw;
                } else {
                    if (accum) {
                        float2 old = *(const float2*)(AccIn + m * ldo + col);
                        x += old.x; y += old.y;
                    }
                    *(float2*)(Out + m * ldo + col) = make_float2(x, y);
                }
            }
        }
    }
    #undef ISSUE
}

// ============ weights-stationary K=64 edge GEMM: Cf = ea@Wc^T + eb1 ==========
#define EP 144
#define EB_OFF 0
#define EA_OFF 18432
#define EA_BYTES 18432
#define EDGE_SMEM (18432 * 3)
#define EMT 8

__global__ void __launch_bounds__(256, 2)
edge_gemm_k64(const h16* __restrict__ A,   // [E, 64] dst-sorted ea
              const h16* __restrict__ B,   // [256, 64] Wc
              const float* __restrict__ bias,
              h16* __restrict__ OutF,      // [E, 256]
              int total_mt) {
    extern __shared__ char smem[];
    const uint32_t sb = smem_u32(smem);
    const int tid = threadIdx.x, lane = tid & 31, wid = tid >> 5;
    const int bn = blockIdx.x * 128;
    const int mt0 = blockIdx.y * EMT;
    const int nt = (total_mt - mt0 < EMT) ? (total_mt - mt0) : EMT;
    const int wm = (wid & 1) * 64;
    const int wn = (wid >> 1) * 32;

    const int lrow = tid >> 1;
    const int lcb  = (tid & 1) * 64;

    #pragma unroll
    for (int i = 0; i < 4; i++) {
        CP16(sb + EB_OFF + lrow * EP + lcb + i * 16,
             B + (bn + lrow) * 64 + lcb / 2 + i * 8);
    }
    #pragma unroll
    for (int i = 0; i < 4; i++) {
        CP16(sb + EA_OFF + lrow * EP + lcb + i * 16,
             A + ((long)mt0 * 128 + lrow) * 64 + lcb / 2 + i * 8);
    }
    asm volatile("cp.async.commit_group;");

    const uint32_t a_off = (uint32_t)((wm + (lane & 15)) * EP + (lane >> 4) * 16);
    const uint32_t b_off = (uint32_t)((lane & 15) * EP + (lane >> 4) * 16);

    const int r0 = lane >> 2;
    const int c0 = (lane & 3) * 2;
    float2 bv[4];
    #pragma unroll
    for (int j = 0; j < 4; j++)
        bv[j] = *(const float2*)&bias[bn + wn + j * 8 + c0];

    for (int t = 0; t < nt; t++) {
        if (t + 1 < nt) {
            const uint32_t ad = sb + EA_OFF + ((t + 1) & 1) * EA_BYTES;
            #pragma unroll
            for (int i = 0; i < 4; i++) {
                CP16(ad + lrow * EP + lcb + i * 16,
                     A + ((long)(mt0 + t + 1) * 128 + lrow) * 64 + lcb / 2 + i * 8);
            }
            asm volatile("cp.async.commit_group;");
            asm volatile("cp.async.wait_group 1;");
        } else {
            asm volatile("cp.async.wait_group 0;");
        }
        __syncthreads();

        float acc[4][4][4];
        #pragma unroll
        for (int i = 0; i < 4; i++)
            #pragma unroll
            for (int j = 0; j < 4; j++)
                #pragma unroll
                for (int q = 0; q < 4; q++) acc[i][j][q] = 0.0f;

        const uint32_t ab = sb + EA_OFF + (t & 1) * EA_BYTES;
        #pragma unroll
        for (int h = 0; h < 4; h++) {
            uint32_t a[4][4];
            #pragma unroll
            for (int mi = 0; mi < 4; mi++)
                LDSM4(a[mi], ab + a_off + mi * (16 * EP) + h * 32);
            uint32_t bq[2][4];
            #pragma unroll
            for (int jj = 0; jj < 2; jj++)
                LDSM4(bq[jj], sb + EB_OFF + b_off + (wn + jj * 16) * EP + h * 32);
            #pragma unroll
            for (int mi = 0; mi < 4; mi++)
                #pragma unroll
                for (int j = 0; j < 4; j++) {
                    const int jj = j >> 1, jo = j & 1;
                    MMA16816(acc[mi][j], a[mi], bq[jj][jo], bq[jj][2 + jo]);
                }
        }

        const long ebase = (long)(mt0 + t) * 128;
        #pragma unroll
        for (int mi = 0; mi < 4; mi++) {
            #pragma unroll
            for (int half = 0; half < 2; half++) {
                const long m = ebase + wm + mi * 16 + r0 + half * 8;
                #pragma unroll
                for (int j = 0; j < 4; j++) {
                    float x = acc[mi][j][half * 2 + 0] + bv[j].x;
                    float y = acc[mi][j][half * 2 + 1] + bv[j].y;
                    const long col = bn + wn + j * 8 + c0;
                    uint32_t hw = ((uint32_t)__half_as_ushort(__float2half(y)) << 16) |
                                  __half_as_ushort(__float2half(x));
                    *(uint32_t*)(OutF + m * 256 + col) = hw;
                }
            }
        }
        __syncthreads();
    }
}

// ====== combine (dst-sorted segmented reduction, no atomics) =================
__global__ void combine_sorted() {
    const int d = blockIdx.x;
    const int col = threadIdx.x;
    const float b = __half2float(g_ABf[(long)d * 512 + 256 + col]);
    const int k0 = g_start[d];
    const int k1 = g_start[d + 1];
    float acc = 0.0f;
    int k = k0;
    for (; k + 2 <= k1; k += 2) {
        const int s0 = g_srcs[k];
        const int s1 = g_srcs[k + 1];
        const float a0 = __half2float(g_ABf[(long)s0 * 512 + col]);
        const float c0 = __half2float(g_Cf[(long)k * 256 + col]);
        const float a1 = __half2float(g_ABf[(long)s1 * 512 + col]);
        const float c1 = __half2float(g_Cf[(long)(k + 1) * 256 + col]);
        acc += silu_f(a0 + b + c0);
        acc += silu_f(a1 + b + c1);
    }
    if (k < k1) {
        const int s0 = g_srcs[k];
        const float a0 = __half2float(g_ABf[(long)s0 * 512 + col]);
        const float c0 = __half2float(g_Cf[(long)k * 256 + col]);
        acc += silu_f(a0 + b + c0);
    }
    g_Pf[(long)d * 256 + col] = __float2half(acc);
}

// ============================ launch =========================================
extern "C" void kernel_launch(void* const* d_in, const int* in_sizes, int n_in,
                              void* d_out, int out_size) {
    const float* node_state = (const float*)d_in[0];
    const float* edge_attr  = (const float*)d_in[1];
    const float* nn_g = (const float*)d_in[2];
    const float* nn_b = (const float*)d_in[3];
    const float* mn_g = (const float*)d_in[4];
    const float* mn_b = (const float*)d_in[5];
    const float* eW1  = (const float*)d_in[6];
    const float* eb1  = (const float*)d_in[7];
    const float* eW2  = (const float*)d_in[8];
    const float* eb2  = (const float*)d_in[9];
    const float* nW1  = (const float*)d_in[10];
    const float* nb1  = (const float*)d_in[11];
    const float* nW2  = (const float*)d_in[12];
    const float* nb2  = (const float*)d_in[13];
    const void*  eidx = d_in[14];
    float* h = (float*)d_out;

    static bool inited = false;
    static cudaStream_t s1;
    static cudaEvent_t evPrep, evG3, evCfree;
    if (!inited) {
        cudaStreamCreateWithFlags(&s1, cudaStreamNonBlocking);
        cudaEventCreateWithFlags(&evPrep,  cudaEventDisableTiming);
        cudaEventCreateWithFlags(&evG3,    cudaEventDisableTiming);
        cudaEventCreateWithFlags(&evCfree, cudaEventDisableTiming);
        cudaFuncSetAttribute(mma_gemm, cudaFuncAttributeMaxDynamicSharedMemorySize,
                             GEMM_SMEM);
        cudaFuncSetAttribute(edge_gemm_k64,
                             cudaFuncAttributeMaxDynamicSharedMemorySize, EDGE_SMEM);
        inited = true;
    }

    void *pY, *pABf, *pCf, *pPf, *pG, *pT, *pEas,
         *pW1, *pWc, *pW2, *pN1, *pN2, *pdeg;
    cudaGetSymbolAddress(&pY, g_Y);     cudaGetSymbolAddress(&pABf, g_ABf);
    cudaGetSymbolAddress(&pCf, g_Cf);   cudaGetSymbolAddress(&pPf, g_Pf);
    cudaGetSymbolAddress(&pG, g_G);     cudaGetSymbolAddress(&pT, g_T);
    cudaGetSymbolAddress(&pEas, g_eas);
    cudaGetSymbolAddress(&pW1, g_W1);   cudaGetSymbolAddress(&pWc, g_Wc);
    cudaGetSymbolAddress(&pW2, g_W2);   cudaGetSymbolAddress(&pN1, g_N1);
    cudaGetSymbolAddress(&pN2, g_N2);   cudaGetSymbolAddress(&pdeg, g_deg);

    h16 *Y=(h16*)pY, *ABf=(h16*)pABf, *Cf=(h16*)pCf, *Pf=(h16*)pPf,
        *T=(h16*)pT, *Eas=(h16*)pEas,
        *W1=(h16*)pW1, *Wc=(h16*)pWc, *W2=(h16*)pW2, *N1=(h16*)pN1,
        *N2=(h16*)pN2;
    float *G=(float*)pG, *deg=(float*)pdeg;

    const int MT = NPAD / 128;                 // 157 node M-tiles
    const int ETOT = N_EDGES / 128;            // 2500 edge M-tiles
    const int EGY = (ETOT + EMT - 1) / EMT;    // 313

    // ---- prep: idx chain on stream 0, weight transpose on s1 (independent) --
    tsplit_all<<<dim3(16, 16, 24), dim3(32, 8), 0, s1>>>(eW1, eW2, nW1, nW2);
    zero_detect<<<(N_NODES + 255) / 256, 256>>>((const long long*)eidx);
    convert_idx_kernel<<<(N_EDGES + 255) / 256, 256>>>(eidx);
    scanA<<<SCB, 256>>>();
    scanB<<<1, 128>>>();
    scanC<<<SCB, 256>>>();
    perm_kernel<<<(N_EDGES + 255) / 256, 256>>>();
    cvt_sorted_kernel<<<((long)N_EDGES * 8 + 255) / 256, 256>>>(edge_attr);
    cudaEventRecord(evPrep, 0);

    // G3(step 0) on s1 (after its own tsplit and main-stream prep)
    cudaStreamWaitEvent(s1, evPrep, 0);
    edge_gemm_k64<<<dim3(2, EGY), 256, EDGE_SMEM, s1>>>(
        Eas, Wc, eb1, Cf, ETOT);
    cudaEventRecord(evG3, s1);

    for (int i = 0; i < S_STEPS; i++) {
        const float* hin = (i == 0) ? node_state : h;

        // main stream: ln -> GEMM-2 (fp16 AB out)
        ln_kernel<<<N_NODES, 256>>>(hin, 256, nn_g + i * HDIM, nn_b + i * HDIM,
                                    nullptr, nullptr, Y, 512, 0);
        mma_gemm<<<dim3(4, MT), 256, GEMM_SMEM>>>(
            Y, 512, W1 + (long)i * 512 * 256, 256,
            nullptr, nullptr, ABf, nullptr, 512, N_NODES, 256, 0, 0);

        // combine (needs this step's Cf)
        cudaStreamWaitEvent(0, evG3, 0);
        combine_sorted<<<N_NODES, 256>>>();
        cudaEventRecord(evCfree, 0);

        // issue NEXT step's edge GEMM on s1 — hides under G5..G8
        if (i + 1 < S_STEPS) {
            cudaStreamWaitEvent(s1, evCfree, 0);
            edge_gemm_k64<<<dim3(2, EGY), 256, EDGE_SMEM, s1>>>(
                Eas, Wc + (long)(i + 1) * 256 * 64, eb1 + (i + 1) * HDIM,
                Cf, ETOT);
            cudaEventRecord(evG3, s1);
        }

        // G5 -> ln -> G7 -> G8
        mma_gemm<<<dim3(2, MT), 256, GEMM_SMEM>>>(
            Pf, 256, W2 + (long)i * 256 * 256, 256,
            nullptr, G, nullptr, nullptr, 256, N_NODES, 256, 0, 0);
        ln_kernel<<<N_NODES, 256>>>(G, 256, mn_g + i * HDIM, mn_b + i * HDIM,
                                    eb2 + i * HDIM, deg, Y, 512, 256);
        mma_gemm<<<dim3(4, MT), 256, GEMM_SMEM>>>(
            Y, 512, N1 + (long)i * 512 * 512, 512,
            nb1 + i * 512, nullptr, T, nullptr, 512, N_NODES, 512, 1, 0);
        mma_gemm<<<dim3(2, MT), 256, GEMM_SMEM>>>(
            T, 512, N2 + (long)i * 256 * 512, 512,
            nb2 + i * HDIM, h, nullptr, hin, 256, N_NODES, 512, 0, 1);
    }
}